// round 13
// baseline (speedup 1.0000x reference)
#include <cuda_runtime.h>
#include <math.h>

#define B 4
#define N 20000
#define M 1024
#define PL 50
#define L_CAP 192   // per-keypoint list capacity (>> max Voronoi occupancy)

// Scratch (allocation-free rule: __device__ globals, zero-initialized at load).
// Pipeline is self-resetting: k_select zeroes counters/sums every launch.
__device__ int    g_p2n[B * N];
__device__ int    g_count[B * M];
__device__ float  g_sumx[B * M];
__device__ float  g_sumy[B * M];
__device__ float  g_sumz[B * M];
__device__ int    g_lidx[B * M * L_CAP];
__device__ float  g_ldst[B * M * L_CAP];
__device__ float  g_partA[512];
__device__ float  g_partW[512];
__device__ int    g_done;

__device__ __forceinline__ unsigned long long pack2(float lo, float hi) {
    unsigned long long d;
    asm("mov.b64 %0, {%1, %2};" : "=l"(d) : "f"(lo), "f"(hi));
    return d;
}

// ---------------- k_assign: per-point argmin over M keypoints ----------------
// One point per thread, TWO m's packed per f32x2 op (even/odd chains).
// CHUNKED two-pass argmin: hot loop is value-only (3 FFMA2 + 2 FMNMX per
// m-pair); chunk winners tracked with strict-< (first chunk keeps ties);
// a <=64-iter rescan of the winning chunk(s) recomputes v (bit-identical)
// and takes the MINIMUM matching m -> exact jnp.argmin first-min semantics.
#define K1_THREADS 64
#define K1_BLKS ((N + K1_THREADS - 1) / K1_THREADS)   // 313
#define MP (M / 2)                                    // 512 m-pairs
#define CHUNK 64
#define NCHUNK (MP / CHUNK)                           // 8

__global__ __launch_bounds__(K1_THREADS) void k_assign(
        const float* __restrict__ pts,
        const float* __restrict__ kp) {
    // sA[mp] = {pack2(kx_e,kx_o), pack2(ky_e,ky_o)}
    // sB[mp] = {pack2(kz_e,kz_o), pack2(kw_e,kw_o)}, kw = 0.5*|k|^2
    __shared__ ulonglong2 sA[MP];
    __shared__ ulonglong2 sB[MP];

    const int b = blockIdx.y;
    const float* kpb = kp + (size_t)b * M * 3;
    for (int mp = threadIdx.x; mp < MP; mp += K1_THREADS) {
        int me = 2 * mp, mo = 2 * mp + 1;
        float ex = kpb[me * 3 + 0], ey = kpb[me * 3 + 1], ez = kpb[me * 3 + 2];
        float ox = kpb[mo * 3 + 0], oy = kpb[mo * 3 + 1], oz = kpb[mo * 3 + 2];
        float ew = 0.5f * (ex * ex + ey * ey + ez * ez);
        float ow_ = 0.5f * (ox * ox + oy * oy + oz * oz);
        ulonglong2 a, c;
        a.x = pack2(ex, ox); a.y = pack2(ey, oy);
        c.x = pack2(ez, oz); c.y = pack2(ew, ow_);
        sA[mp] = a;
        sB[mp] = c;
    }
    __syncthreads();

    const int p = blockIdx.x * K1_THREADS + threadIdx.x;
    float x = 0.f, y = 0.f, z = 0.f;
    if (p < N) {
        const float* q = pts + ((size_t)b * N + p) * 3;
        x = q[0]; y = q[1]; z = q[2];
    }
    const unsigned long long nx2 = pack2(-x, -x);
    const unsigned long long ny2 = pack2(-y, -y);
    const unsigned long long nz2 = pack2(-z, -z);

    float gve = INFINITY, gvo = INFINITY;
    int che = 0, cho = 0;     // first chunk achieving each chain's min

    for (int ch = 0; ch < NCHUNK; ch++) {
        float cve = INFINITY, cvo = INFINITY;
        const int base = ch * CHUNK;
#pragma unroll 8
        for (int k = 0; k < CHUNK; k++) {
            ulonglong2 a = sA[base + k];
            ulonglong2 c = sB[base + k];
            unsigned long long v2;
            // v = 0.5|k|^2 - k.p  (monotone in true sq-dist for fixed point)
            asm("fma.rn.f32x2 %0, %1, %2, %3;" : "=l"(v2) : "l"(c.x), "l"(nz2), "l"(c.y));
            asm("fma.rn.f32x2 %0, %1, %2, %3;" : "=l"(v2) : "l"(a.y), "l"(ny2), "l"(v2));
            asm("fma.rn.f32x2 %0, %1, %2, %3;" : "=l"(v2) : "l"(a.x), "l"(nx2), "l"(v2));
            float v0, v1;
            asm("mov.b64 {%0, %1}, %2;" : "=f"(v0), "=f"(v1) : "l"(v2));
            cve = fminf(cve, v0);
            cvo = fminf(cvo, v1);
        }
        // strict <: first chunk keeps ties
        bool be = cve < gve; che = be ? ch : che; gve = fminf(gve, cve);
        bool bo = cvo < gvo; cho = bo ? ch : cho; gvo = fminf(gvo, cvo);
    }

    if (p < N) {
        float gmin = fminf(gve, gvo);
        bool evalid = (gve == gmin), ovalid = (gvo == gmin);

        int chunks[2]; int nch = 0;
        if (evalid) chunks[nch++] = che;
        if (ovalid && (!evalid || cho != che)) chunks[nch++] = cho;

        int cand = 0x7fffffff;
        for (int q2 = 0; q2 < nch; q2++) {
            int cbase = chunks[q2] * CHUNK;
            bool okE = evalid && (chunks[q2] == che);
            bool okO = ovalid && (chunks[q2] == cho);
            for (int k = 0; k < CHUNK; k++) {
                ulonglong2 a = sA[cbase + k];
                ulonglong2 c = sB[cbase + k];
                unsigned long long v2;
                asm("fma.rn.f32x2 %0, %1, %2, %3;" : "=l"(v2) : "l"(c.x), "l"(nz2), "l"(c.y));
                asm("fma.rn.f32x2 %0, %1, %2, %3;" : "=l"(v2) : "l"(a.y), "l"(ny2), "l"(v2));
                asm("fma.rn.f32x2 %0, %1, %2, %3;" : "=l"(v2) : "l"(a.x), "l"(nx2), "l"(v2));
                float v0, v1;
                asm("mov.b64 {%0, %1}, %2;" : "=f"(v0), "=f"(v1) : "l"(v2));
                int me = 2 * (cbase + k);
                if (okE && v0 == gmin) cand = min(cand, me);
                if (okO && v1 == gmin) cand = min(cand, me + 1);
            }
        }

        int bestm = cand;
        int gi = b * N + p;
        int bm = b * M + bestm;
        float pp = x * x + y * y + z * z;
        float dist = fmaf(2.0f, gmin, pp);       // true squared distance
        g_p2n[gi] = bestm;
        // coordinate sums (no-return atomics -> RED.ADD)
        atomicAdd(&g_sumx[bm], x);
        atomicAdd(&g_sumy[bm], y);
        atomicAdd(&g_sumz[bm], z);
        int pos = atomicAdd(&g_count[bm], 1);
        if (pos < L_CAP) {
            g_lidx[(size_t)bm * L_CAP + pos] = p;
            g_ldst[(size_t)bm * L_CAP + pos] = dist;
        }
    }
}

// ---------------- k_select: one WARP per (b, m), fused final reduce ---------
#define SEL_THREADS 256
#define SEL_WARPS (SEL_THREADS / 32)      // 8
#define SEL_BLOCKS (B * M / SEL_WARPS)    // 512
#define SLOTS (L_CAP / 32)                // 6 keys per lane

__global__ __launch_bounds__(SEL_THREADS) void k_select(
        const float* __restrict__ pts,
        const float* __restrict__ kpw,
        const float* __restrict__ pose,
        const float* __restrict__ ow,
        float* __restrict__ out) {
    __shared__ float s_a[SEL_WARPS];
    __shared__ float s_w[SEL_WARPS];
    __shared__ int s_last;

    int wg = (blockIdx.x * SEL_THREADS + threadIdx.x) >> 5;   // global warp id
    int wid = threadIdx.x >> 5;
    int lane = threadIdx.x & 31;
    int b = wg / M;
    int m = wg - b * M;
    int i = wg;

    const float* ptsb = pts + (size_t)b * N * 3;
    const int* p2nb = g_p2n + (size_t)b * N;

    // Independent loads up front (all L2-resident from k_assign's writes).
    int c = g_count[i];
    float ssx = g_sumx[i];
    float ssy = g_sumy[i];
    float ssz = g_sumz[i];
    int pv = p2nb[lane];               // prefetch first filler window

    if (lane == 0) {                   // self-reset for next replay
        g_count[i] = 0;
        g_sumx[i] = 0.f; g_sumy[i] = 0.f; g_sumz[i] = 0.f;
    }

    float sx = 0.f, sy = 0.f, sz = 0.f;
    int fill;

    if (c <= PL) {
        // Sum already computed by k_assign's RED.ADD — no gather needed.
        if (lane == 0) { sx = ssx; sy = ssy; sz = ssz; }
        fill = PL - c;
    } else {
        // RANK selection: key = (enc(dist)<<32)|idx is unique => total order
        // => rank(k) = #{k' < k}; rank < 50 is EXACTLY the stable top_k set.
        // Ranks computed by broadcasting slot registers across lanes —
        // throughput ops only, no serial extraction chains.
        const int* lidx = g_lidx + (size_t)i * L_CAP;
        const float* ldst = g_ldst + (size_t)i * L_CAP;
        int cc = min(c, L_CAP);
        int su = (cc + 31) >> 5;       // slot rounds holding real keys

        unsigned long long ks[SLOTS];
#pragma unroll
        for (int t = 0; t < SLOTS; t++) {
            int j = lane + 32 * t;
            unsigned long long key = ~0ull;         // sentinel = +inf
            if (j < cc) {
                float d = ldst[j];
                unsigned u = __float_as_uint(d);
                unsigned enc = (u & 0x80000000u) ? ~u : (u | 0x80000000u);
                key = ((unsigned long long)enc << 32) | (unsigned)lidx[j];
            }
            ks[t] = key;
        }

        unsigned cnt[SLOTS] = {0, 0, 0, 0, 0, 0};
        for (int t2 = 0; t2 < su; t2++) {
            unsigned long long kslot = ks[t2];
#pragma unroll 4
            for (int src = 0; src < 32; src++) {
                unsigned long long kk =
                    __shfl_sync(0xffffffffu, kslot, src);
#pragma unroll
                for (int t = 0; t < SLOTS; t++) cnt[t] += (kk < ks[t]);
            }
        }

        // Gather selected points (exactly 50 across the warp, <=6 per lane).
#pragma unroll
        for (int t = 0; t < SLOTS; t++) {
            if (cnt[t] < PL) {
                unsigned idx = (unsigned)ks[t];
                const float* q = &ptsb[(size_t)idx * 3];
                sx += q[0]; sy += q[1]; sz += q[2];
            }
        }
        fill = 0;
    }

    // Fillers: first (50 - c) point indices with p2n != m (FAR pad, stable
    // tie-break = ascending index). Warp-cooperative ballot sweep.
    int n0 = 0;
    while (fill > 0) {
        int n = n0 + lane;                 // n stays far below N (fill <= 50)
        int pn = (n0 == 0) ? pv : p2nb[n];
        bool ok = (pn != m);
        unsigned msk = __ballot_sync(0xffffffffu, ok);
        int rank = __popc(msk & ((1u << lane) - 1u));
        if (ok && rank < fill) {
            const float* q = &ptsb[(size_t)n * 3];
            sx += q[0]; sy += q[1]; sz += q[2];
        }
        fill -= min(fill, __popc(msk));
        n0 += 32;
    }

    // Warp reduce
#pragma unroll
    for (int off = 16; off; off >>= 1) {
        sx += __shfl_xor_sync(0xffffffffu, sx, off);
        sy += __shfl_xor_sync(0xffffffffu, sy, off);
        sz += __shfl_xor_sync(0xffffffffu, sz, off);
    }

    if (lane == 0) {
        // mean(R p + t) = R mean(p) + t
        const float* P = pose + b * 16;
        float mx = sx * (1.0f / PL), my = sy * (1.0f / PL), mz = sz * (1.0f / PL);
        float ex = P[0] * mx + P[1] * my + P[2]  * mz + P[3]  - kpw[i * 3 + 0];
        float ey = P[4] * mx + P[5] * my + P[6]  * mz + P[7]  - kpw[i * 3 + 1];
        float ez = P[8] * mx + P[9] * my + P[10] * mz + P[11] - kpw[i * 3 + 2];
        float w = ow[i];
        s_a[wid] = w * (fabsf(ex) + fabsf(ey) + fabsf(ez));
        s_w[wid] = w;
    }
    __syncthreads();

    // One plain store per block, then ticket; last block reduces partials.
    if (threadIdx.x == 0) {
        float ba = 0.f, bw = 0.f;
#pragma unroll
        for (int k = 0; k < SEL_WARPS; k++) { ba += s_a[k]; bw += s_w[k]; }
        g_partA[blockIdx.x] = ba;
        g_partW[blockIdx.x] = bw;
        __threadfence();
        int t = atomicAdd(&g_done, 1);
        s_last = (t == SEL_BLOCKS - 1);
    }
    __syncthreads();

    if (s_last) {
        __threadfence();
        float a = 0.f, w = 0.f;
        for (int k = threadIdx.x; k < SEL_BLOCKS; k += SEL_THREADS) {
            a += g_partA[k];
            w += g_partW[k];
        }
#pragma unroll
        for (int off = 16; off; off >>= 1) {
            a += __shfl_xor_sync(0xffffffffu, a, off);
            w += __shfl_xor_sync(0xffffffffu, w, off);
        }
        if (lane == 0) { s_a[wid] = a; s_w[wid] = w; }
        __syncthreads();
        if (threadIdx.x == 0) {
            double A = 0.0, W = 0.0;
#pragma unroll
            for (int k = 0; k < SEL_WARPS; k++) { A += s_a[k]; W += s_w[k]; }
            if (W < 1e-6) W = 1e-6;
            out[0] = (float)(A / W);
            g_done = 0;                 // self-reset for next replay
            __threadfence();
        }
    }
}

extern "C" void kernel_launch(void* const* d_in, const int* in_sizes, int n_in,
                              void* d_out, int out_size) {
    const float* pts  = (const float*)d_in[0];  // (B, N, 3)
    const float* kp   = (const float*)d_in[1];  // (B, M, 3)
    const float* kpw  = (const float*)d_in[2];  // (B, M, 3)
    const float* pose = (const float*)d_in[3];  // (B, 4, 4)
    const float* ow   = (const float*)d_in[4];  // (B, M)
    float* out = (float*)d_out;

    dim3 g1(K1_BLKS, B);
    k_assign<<<g1, K1_THREADS>>>(pts, kp);

    k_select<<<SEL_BLOCKS, SEL_THREADS>>>(pts, kpw, pose, ow, out);
}

// round 14
// speedup vs baseline: 1.5223x; 1.5223x over previous
#include <cuda_runtime.h>
#include <math.h>

#define B 4
#define N 20000
#define M 1024
#define PL 50
#define L_CAP 192   // per-keypoint list capacity (>> max Voronoi occupancy)

// Scratch (allocation-free rule: __device__ globals, zero-initialized at load).
// Pipeline is self-resetting: k_select zeroes counters/sums every launch.
__device__ int    g_p2n[B * N];
__device__ int    g_count[B * M];
__device__ float  g_sumx[B * M];
__device__ float  g_sumy[B * M];
__device__ float  g_sumz[B * M];
__device__ int    g_lidx[B * M * L_CAP];
__device__ float  g_ldst[B * M * L_CAP];
__device__ float  g_partA[512];
__device__ float  g_partW[512];
__device__ int    g_done;

__device__ __forceinline__ unsigned long long pack2(float lo, float hi) {
    unsigned long long d;
    asm("mov.b64 %0, {%1, %2};" : "=l"(d) : "f"(lo), "f"(hi));
    return d;
}

// ---------------- k_assign: per-point argmin over M keypoints ----------------
// ROUND-10 VERSION (best measured ~22.5us): one point per thread, TWO m's
// packed per f32x2 op (even/odd min chains), single pass. Value-min via fminf
// (FMNMX -> alu pipe), index select integer SEL (alu). Epilogue: per-keypoint
// coordinate sums via no-return float atomics (RED.ADD).
#define K1_THREADS 64
#define K1_BLKS ((N + K1_THREADS - 1) / K1_THREADS)   // 313
#define MP (M / 2)                                    // 512 m-pairs

__global__ __launch_bounds__(K1_THREADS) void k_assign(
        const float* __restrict__ pts,
        const float* __restrict__ kp) {
    // sA[mp] = {pack2(kx_e,kx_o), pack2(ky_e,ky_o)}
    // sB[mp] = {pack2(kz_e,kz_o), pack2(kw_e,kw_o)}, kw = 0.5*|k|^2
    __shared__ ulonglong2 sA[MP];
    __shared__ ulonglong2 sB[MP];

    const int b = blockIdx.y;
    const float* kpb = kp + (size_t)b * M * 3;
    for (int mp = threadIdx.x; mp < MP; mp += K1_THREADS) {
        int me = 2 * mp, mo = 2 * mp + 1;
        float ex = kpb[me * 3 + 0], ey = kpb[me * 3 + 1], ez = kpb[me * 3 + 2];
        float ox = kpb[mo * 3 + 0], oy = kpb[mo * 3 + 1], oz = kpb[mo * 3 + 2];
        float ew = 0.5f * (ex * ex + ey * ey + ez * ez);
        float ow_ = 0.5f * (ox * ox + oy * oy + oz * oz);
        ulonglong2 a, c;
        a.x = pack2(ex, ox); a.y = pack2(ey, oy);
        c.x = pack2(ez, oz); c.y = pack2(ew, ow_);
        sA[mp] = a;
        sB[mp] = c;
    }
    __syncthreads();

    const int p = blockIdx.x * K1_THREADS + threadIdx.x;
    float x = 0.f, y = 0.f, z = 0.f;
    if (p < N) {
        const float* q = pts + ((size_t)b * N + p) * 3;
        x = q[0]; y = q[1]; z = q[2];
    }
    unsigned long long nx2 = pack2(-x, -x);
    unsigned long long ny2 = pack2(-y, -y);
    unsigned long long nz2 = pack2(-z, -z);

    float bve = INFINITY, bvo = INFINITY;
    int bme = 0, bmo = 0;       // m-pair indices for even/odd chains

#pragma unroll 8
    for (int mp = 0; mp < MP; mp++) {
        ulonglong2 a = sA[mp];
        ulonglong2 c = sB[mp];
        unsigned long long v2;
        // v = 0.5|k|^2 - k.p  (monotone in true sq-dist for a fixed point)
        asm("fma.rn.f32x2 %0, %1, %2, %3;" : "=l"(v2) : "l"(c.x), "l"(nz2), "l"(c.y));
        asm("fma.rn.f32x2 %0, %1, %2, %3;" : "=l"(v2) : "l"(a.y), "l"(ny2), "l"(v2));
        asm("fma.rn.f32x2 %0, %1, %2, %3;" : "=l"(v2) : "l"(a.x), "l"(nx2), "l"(v2));
        float v0, v1;
        asm("mov.b64 {%0, %1}, %2;" : "=f"(v0), "=f"(v1) : "l"(v2));
        // strict <: keeps FIRST minimum within each chain (ascending m).
        bool le = v0 < bve;
        bme = le ? mp : bme;
        bve = fminf(bve, v0);
        bool lo = v1 < bvo;
        bmo = lo ? mp : bmo;
        bvo = fminf(bvo, v1);
    }

    if (p < N) {
        // Merge chains. Global first-min: odd wins only if strictly smaller, or
        // equal with smaller m (2*bmo+1 < 2*bme only if bmo < bme).
        int me = 2 * bme, mo = 2 * bmo + 1;
        bool ow2 = (bvo < bve) || (bvo == bve && mo < me);
        float bestv = ow2 ? bvo : bve;
        int bestm = ow2 ? mo : me;

        int gi = b * N + p;
        int bm = b * M + bestm;
        float pp = x * x + y * y + z * z;
        float dist = fmaf(2.0f, bestv, pp);      // true squared distance
        g_p2n[gi] = bestm;
        // coordinate sums (no-return atomics -> RED.ADD)
        atomicAdd(&g_sumx[bm], x);
        atomicAdd(&g_sumy[bm], y);
        atomicAdd(&g_sumz[bm], z);
        int pos = atomicAdd(&g_count[bm], 1);
        if (pos < L_CAP) {
            g_lidx[(size_t)bm * L_CAP + pos] = p;
            g_ldst[(size_t)bm * L_CAP + pos] = dist;
        }
    }
}

// ---------------- k_select: one WARP per (b, m), fused final reduce ---------
// ROUND-13 VERSION (best measured 14.0us): rank selection for the rare c>50
// path — no serial extraction chains.
#define SEL_THREADS 256
#define SEL_WARPS (SEL_THREADS / 32)      // 8
#define SEL_BLOCKS (B * M / SEL_WARPS)    // 512
#define SLOTS (L_CAP / 32)                // 6 keys per lane

__global__ __launch_bounds__(SEL_THREADS) void k_select(
        const float* __restrict__ pts,
        const float* __restrict__ kpw,
        const float* __restrict__ pose,
        const float* __restrict__ ow,
        float* __restrict__ out) {
    __shared__ float s_a[SEL_WARPS];
    __shared__ float s_w[SEL_WARPS];
    __shared__ int s_last;

    int wg = (blockIdx.x * SEL_THREADS + threadIdx.x) >> 5;   // global warp id
    int wid = threadIdx.x >> 5;
    int lane = threadIdx.x & 31;
    int b = wg / M;
    int m = wg - b * M;
    int i = wg;

    const float* ptsb = pts + (size_t)b * N * 3;
    const int* p2nb = g_p2n + (size_t)b * N;

    // Independent loads up front (all L2-resident from k_assign's writes).
    int c = g_count[i];
    float ssx = g_sumx[i];
    float ssy = g_sumy[i];
    float ssz = g_sumz[i];
    int pv = p2nb[lane];               // prefetch first filler window

    if (lane == 0) {                   // self-reset for next replay
        g_count[i] = 0;
        g_sumx[i] = 0.f; g_sumy[i] = 0.f; g_sumz[i] = 0.f;
    }

    float sx = 0.f, sy = 0.f, sz = 0.f;
    int fill;

    if (c <= PL) {
        // Sum already computed by k_assign's RED.ADD — no gather needed.
        if (lane == 0) { sx = ssx; sy = ssy; sz = ssz; }
        fill = PL - c;
    } else {
        // RANK selection: key = (enc(dist)<<32)|idx is unique => total order
        // => rank(k) = #{k' < k}; rank < 50 is EXACTLY the stable top_k set.
        // Ranks computed by broadcasting slot registers across lanes —
        // throughput ops only, no serial extraction chains.
        const int* lidx = g_lidx + (size_t)i * L_CAP;
        const float* ldst = g_ldst + (size_t)i * L_CAP;
        int cc = min(c, L_CAP);
        int su = (cc + 31) >> 5;       // slot rounds holding real keys

        unsigned long long ks[SLOTS];
#pragma unroll
        for (int t = 0; t < SLOTS; t++) {
            int j = lane + 32 * t;
            unsigned long long key = ~0ull;         // sentinel = +inf
            if (j < cc) {
                float d = ldst[j];
                unsigned u = __float_as_uint(d);
                unsigned enc = (u & 0x80000000u) ? ~u : (u | 0x80000000u);
                key = ((unsigned long long)enc << 32) | (unsigned)lidx[j];
            }
            ks[t] = key;
        }

        unsigned cnt[SLOTS] = {0, 0, 0, 0, 0, 0};
        for (int t2 = 0; t2 < su; t2++) {
            unsigned long long kslot = ks[t2];
#pragma unroll 4
            for (int src = 0; src < 32; src++) {
                unsigned long long kk =
                    __shfl_sync(0xffffffffu, kslot, src);
#pragma unroll
                for (int t = 0; t < SLOTS; t++) cnt[t] += (kk < ks[t]);
            }
        }

        // Gather selected points (exactly 50 across the warp, <=6 per lane).
#pragma unroll
        for (int t = 0; t < SLOTS; t++) {
            if (cnt[t] < PL) {
                unsigned idx = (unsigned)ks[t];
                const float* q = &ptsb[(size_t)idx * 3];
                sx += q[0]; sy += q[1]; sz += q[2];
            }
        }
        fill = 0;
    }

    // Fillers: first (50 - c) point indices with p2n != m (FAR pad, stable
    // tie-break = ascending index). Warp-cooperative ballot sweep.
    int n0 = 0;
    while (fill > 0) {
        int n = n0 + lane;                 // n stays far below N (fill <= 50)
        int pn = (n0 == 0) ? pv : p2nb[n];
        bool ok = (pn != m);
        unsigned msk = __ballot_sync(0xffffffffu, ok);
        int rank = __popc(msk & ((1u << lane) - 1u));
        if (ok && rank < fill) {
            const float* q = &ptsb[(size_t)n * 3];
            sx += q[0]; sy += q[1]; sz += q[2];
        }
        fill -= min(fill, __popc(msk));
        n0 += 32;
    }

    // Warp reduce
#pragma unroll
    for (int off = 16; off; off >>= 1) {
        sx += __shfl_xor_sync(0xffffffffu, sx, off);
        sy += __shfl_xor_sync(0xffffffffu, sy, off);
        sz += __shfl_xor_sync(0xffffffffu, sz, off);
    }

    if (lane == 0) {
        // mean(R p + t) = R mean(p) + t
        const float* P = pose + b * 16;
        float mx = sx * (1.0f / PL), my = sy * (1.0f / PL), mz = sz * (1.0f / PL);
        float ex = P[0] * mx + P[1] * my + P[2]  * mz + P[3]  - kpw[i * 3 + 0];
        float ey = P[4] * mx + P[5] * my + P[6]  * mz + P[7]  - kpw[i * 3 + 1];
        float ez = P[8] * mx + P[9] * my + P[10] * mz + P[11] - kpw[i * 3 + 2];
        float w = ow[i];
        s_a[wid] = w * (fabsf(ex) + fabsf(ey) + fabsf(ez));
        s_w[wid] = w;
    }
    __syncthreads();

    // One plain store per block, then ticket; last block reduces partials.
    if (threadIdx.x == 0) {
        float ba = 0.f, bw = 0.f;
#pragma unroll
        for (int k = 0; k < SEL_WARPS; k++) { ba += s_a[k]; bw += s_w[k]; }
        g_partA[blockIdx.x] = ba;
        g_partW[blockIdx.x] = bw;
        __threadfence();
        int t = atomicAdd(&g_done, 1);
        s_last = (t == SEL_BLOCKS - 1);
    }
    __syncthreads();

    if (s_last) {
        __threadfence();
        float a = 0.f, w = 0.f;
        for (int k = threadIdx.x; k < SEL_BLOCKS; k += SEL_THREADS) {
            a += g_partA[k];
            w += g_partW[k];
        }
#pragma unroll
        for (int off = 16; off; off >>= 1) {
            a += __shfl_xor_sync(0xffffffffu, a, off);
            w += __shfl_xor_sync(0xffffffffu, w, off);
        }
        if (lane == 0) { s_a[wid] = a; s_w[wid] = w; }
        __syncthreads();
        if (threadIdx.x == 0) {
            double A = 0.0, W = 0.0;
#pragma unroll
            for (int k = 0; k < SEL_WARPS; k++) { A += s_a[k]; W += s_w[k]; }
            if (W < 1e-6) W = 1e-6;
            out[0] = (float)(A / W);
            g_done = 0;                 // self-reset for next replay
            __threadfence();
        }
    }
}

extern "C" void kernel_launch(void* const* d_in, const int* in_sizes, int n_in,
                              void* d_out, int out_size) {
    const float* pts  = (const float*)d_in[0];  // (B, N, 3)
    const float* kp   = (const float*)d_in[1];  // (B, M, 3)
    const float* kpw  = (const float*)d_in[2];  // (B, M, 3)
    const float* pose = (const float*)d_in[3];  // (B, 4, 4)
    const float* ow   = (const float*)d_in[4];  // (B, M)
    float* out = (float*)d_out;

    dim3 g1(K1_BLKS, B);
    k_assign<<<g1, K1_THREADS>>>(pts, kp);

    k_select<<<SEL_BLOCKS, SEL_THREADS>>>(pts, kpw, pose, ow, out);
}